// round 2
// baseline (speedup 1.0000x reference)
#include <cuda_runtime.h>
#include <math.h>

#define TPB   320
#define NPOS  289   // 17*17
#define TILE_CH 756 // 27*28
#define TILE_SZ (3*756)

__global__ __launch_bounds__(TPB)
void topo_kernel(const float* __restrict__ state, float* __restrict__ out, int nb)
{
    const int b   = blockIdx.x;
    const int tid = threadIdx.x;

    __shared__ float tile[TILE_SZ];
    __shared__ float red[64];

    // Zero-haloed tile: [ch][27 rows][28 cols], data at rows/cols 4..22
    for (int i = tid; i < TILE_SZ; i += TPB) tile[i] = 0.f;
    __syncthreads();

    const float* sp = state + (size_t)b * 1083;  // 19*19*3, NHWC
    for (int i = tid; i < 1083; i += TPB) {
        int y   = i / 57;
        int rem = i - y * 57;
        int x   = rem / 3;
        int ch  = rem - x * 3;
        tile[ch * TILE_CH + (y + 4) * 28 + (x + 4)] = sp[i];
    }
    __syncthreads();

    float logit, dval;
    if (tid < NPOS) {
        const int py = tid / 17;
        const int px = tid - py * 17;
        const int r0 = py + 5;      // core excludes border -> center at (py+1, px+1) + halo 4
        const int c0 = px + 5;
        const int base0 = r0 * 28 + c0;

        const int DR[4] = {0, 1, 1, 1};
        const int DC[4] = {1, 0, 1, -1};

        float sd0 = 0.f, sd1 = 0.f;

        #pragma unroll
        for (int o = 0; o < 4; ++o) {
            const int step = DR[o] * 28 + DC[o];
            float v[3][9];
            #pragma unroll
            for (int t = 0; t < 9; ++t) {
                int idx = base0 + step * (t - 4);
                v[0][t] = tile[idx];
                v[1][t] = tile[TILE_CH + idx];
                v[2][t] = tile[2 * TILE_CH + idx];
            }
            // sliding 5-window sums: w[ch][q] = sum v[ch][4-q .. 8-q]
            float w[3][5];
            #pragma unroll
            for (int ch = 0; ch < 3; ++ch) {
                float acc = v[ch][4] + v[ch][5] + v[ch][6] + v[ch][7] + v[ch][8];
                w[ch][0] = acc;
                #pragma unroll
                for (int q = 1; q <= 4; ++q) {
                    acc += v[ch][4 - q] - v[ch][9 - q];
                    w[ch][q] = acc;
                }
            }
            float s0 = 0.f, s1 = 0.f;
            #pragma unroll
            for (int q = 0; q < 5; ++q) {
                float a12 = w[1][q] + w[2][q];
                float rr0 = fmaf(-6.f, v[0][4], w[0][q]);
                rr0 = fmaf(-5.f, a12, rr0);
                rr0 = fmaxf(rr0, 0.f);
                float c2 = rr0 * rr0, c4 = c2 * c2;
                s0 = fmaf(c4, c2, s0);

                float a02 = w[0][q] + w[2][q];
                float rr1 = fmaf(-6.f, v[1][4], w[1][q]);
                rr1 = fmaf(-5.f, a02, rr1);
                rr1 = fmaxf(rr1, 0.f);
                float d2 = rr1 * rr1, d4 = d2 * d2;
                s1 = fmaf(d4, d2, s1);
            }
            sd0 += (s0 > 0.f) ? __powf(s0, 0.83333333f) : 0.f;   // 5/6
            sd1 += (s1 > 0.f) ? __powf(s1, 0.83333333f) : 0.f;
        }
        float f0 = (sd0 > 0.f) ? __powf(sd0, 0.2f) : 0.f;        // 1/5
        float f1 = (sd1 > 0.f) ? __powf(sd1, 0.2f) : 0.f;
        logit = f0 + f1;
        dval  = f0 - f1;
    } else {
        logit = -INFINITY;
        dval  = 0.f;
    }

    const unsigned FULL = 0xffffffffu;
    const int wid  = tid >> 5;
    const int lane = tid & 31;

    // ---- block max of logits ----
    float m = logit;
    #pragma unroll
    for (int off = 16; off; off >>= 1)
        m = fmaxf(m, __shfl_xor_sync(FULL, m, off));
    if (lane == 0) red[wid] = m;
    __syncthreads();
    if (tid < 32) {
        float t = (tid < TPB / 32) ? red[tid] : -INFINITY;
        #pragma unroll
        for (int off = 8; off; off >>= 1)
            t = fmaxf(t, __shfl_xor_sync(FULL, t, off));
        if (tid == 0) red[32] = t;
    }
    __syncthreads();
    const float maxv = red[32];

    // ---- sum of exp and sum of (f0 - f1) ----
    float e  = (tid < NPOS) ? __expf(2.f * (logit - maxv)) : 0.f;  // POLICY_STRETCH = 2
    float se = e, sv = dval;
    #pragma unroll
    for (int off = 16; off; off >>= 1) {
        se += __shfl_xor_sync(FULL, se, off);
        sv += __shfl_xor_sync(FULL, sv, off);
    }
    if (lane == 0) { red[wid] = se; red[wid + 16] = sv; }
    __syncthreads();
    if (tid < 32) {
        float a  = (tid < TPB / 32) ? red[tid] : 0.f;
        float bb = (tid < TPB / 32) ? red[tid + 16] : 0.f;
        #pragma unroll
        for (int off = 8; off; off >>= 1) {
            a  += __shfl_xor_sync(FULL, a, off);
            bb += __shfl_xor_sync(FULL, bb, off);
        }
        if (tid == 0) { red[33] = a; red[34] = bb; }
    }
    __syncthreads();

    if (tid < NPOS)
        out[(size_t)b * NPOS + tid] = e * (1.f / red[33]);
    if (tid == 0)
        out[(size_t)nb * NPOS + b] = tanhf(red[34] * (0.2f / 32.f)); // tanh(VALUE_STRETCH*VALUE_GAUGE*D)
}

extern "C" void kernel_launch(void* const* d_in, const int* in_sizes, int n_in,
                              void* d_out, int out_size)
{
    const float* state = (const float*)d_in[0];
    const int nb = in_sizes[0] / (19 * 19 * 3);
    topo_kernel<<<nb, TPB>>>(state, (float*)d_out, nb);
}

// round 4
// speedup vs baseline: 1.3571x; 1.3571x over previous
#include <cuda_runtime.h>
#include <math.h>

#define TPB    320
#define NPOS   289        // 17*17 core positions
#define TW     28         // padded tile width (27 rows x 28 cols)
#define TCELLS (27*28)

__global__ __launch_bounds__(TPB)
void topo_kernel(const float* __restrict__ state, float* __restrict__ out, int nb)
{
    const int b   = blockIdx.x;
    const int tid = threadIdx.x;

    __shared__ float2 g[TCELLS];    // (g0,g1) = channel-combined cell values, zero halo
    __shared__ float2 xc[TCELLS];   // (x0,x1) raw values, read only at centers
    __shared__ float  red[64];

    // phase 0a: zero-halo the combined tile
    for (int i = tid; i < TCELLS; i += TPB) g[i] = make_float2(0.f, 0.f);
    __syncthreads();

    // phase 0b: load 19x19x3 NHWC, fold channels: g0 = x0-5(x1+x2), g1 = x1-5(x0+x2)
    const float* sp = state + (size_t)b * 1083;
    for (int i = tid; i < 361; i += TPB) {
        int y = i / 19, x = i - y * 19;
        float x0 = sp[3 * i], x1 = sp[3 * i + 1], x2 = sp[3 * i + 2];
        int idx = (y + 4) * TW + (x + 4);
        g[idx]  = make_float2(fmaf(-5.f, x1 + x2, x0), fmaf(-5.f, x0 + x2, x1));
        xc[idx] = make_float2(x0, x1);
    }
    __syncthreads();

    float logit, dval;
    if (tid < NPOS) {
        const int py = tid / 17;
        const int px = tid - py * 17;
        const int base = (py + 5) * TW + (px + 5);   // core offset 1 + halo 4

        const float2 cx = xc[base];
        const float c0 = 6.f * cx.x;
        const float c1 = 6.f * cx.y;

        const int steps[4] = {1, TW, TW + 1, TW - 1};  // H, V, diag, anti-diag
        float sd0 = 0.f, sd1 = 0.f;

        #pragma unroll
        for (int o = 0; o < 4; ++o) {
            const int st = steps[o];
            float2 d[9];
            #pragma unroll
            for (int t = 0; t < 9; ++t) d[t] = g[base + st * (t - 4)];

            // sliding 5-window sums over the combined values
            float u = d[4].x + d[5].x + d[6].x + d[7].x + d[8].x;
            float v = d[4].y + d[5].y + d[6].y + d[7].y + d[8].y;
            float s0 = 0.f, s1 = 0.f;
            #pragma unroll
            for (int q = 0; q < 5; ++q) {
                if (q) {
                    u += d[4 - q].x - d[9 - q].x;
                    v += d[4 - q].y - d[9 - q].y;
                }
                float r0 = fmaxf(u - c0, 0.f);          // relu(conv)
                float a2 = r0 * r0, a4 = a2 * a2;
                s0 = fmaf(a4, a2, s0);                  // += r0^6
                float r1 = fmaxf(v - c1, 0.f);
                float b2 = r1 * r1, b4 = b2 * b2;
                s1 = fmaf(b4, b2, s1);
            }
            sd0 += (s0 > 0.f) ? __powf(s0, 0.8333333333f) : 0.f;   // ^(5/6)
            sd1 += (s1 > 0.f) ? __powf(s1, 0.8333333333f) : 0.f;
        }
        float f0 = (sd0 > 0.f) ? __powf(sd0, 0.2f) : 0.f;          // ^(1/5)
        float f1 = (sd1 > 0.f) ? __powf(sd1, 0.2f) : 0.f;
        logit = f0 + f1;
        dval  = f0 - f1;
    } else {
        logit = -INFINITY;
        dval  = 0.f;
    }

    const unsigned FULL = 0xffffffffu;
    const int wid  = tid >> 5;
    const int lane = tid & 31;

    // block max of logits
    float m = logit;
    #pragma unroll
    for (int off = 16; off; off >>= 1)
        m = fmaxf(m, __shfl_xor_sync(FULL, m, off));
    if (lane == 0) red[wid] = m;
    __syncthreads();
    if (tid < 32) {
        float t = (tid < TPB / 32) ? red[tid] : -INFINITY;
        #pragma unroll
        for (int off = 8; off; off >>= 1)
            t = fmaxf(t, __shfl_xor_sync(FULL, t, off));
        if (tid == 0) red[32] = t;
    }
    __syncthreads();
    const float maxv = red[32];

    // sum of exp (softmax denom) and sum of (f0 - f1) (value head)
    float e  = (tid < NPOS) ? __expf(2.f * (logit - maxv)) : 0.f;  // POLICY_STRETCH = 2
    float se = e, sv = dval;
    #pragma unroll
    for (int off = 16; off; off >>= 1) {
        se += __shfl_xor_sync(FULL, se, off);
        sv += __shfl_xor_sync(FULL, sv, off);
    }
    if (lane == 0) { red[wid] = se; red[wid + 16] = sv; }
    __syncthreads();
    if (tid < 32) {
        float a  = (tid < TPB / 32) ? red[tid] : 0.f;
        float bb = (tid < TPB / 32) ? red[tid + 16] : 0.f;
        #pragma unroll
        for (int off = 8; off; off >>= 1) {
            a  += __shfl_xor_sync(FULL, a, off);
            bb += __shfl_xor_sync(FULL, bb, off);
        }
        if (tid == 0) { red[33] = a; red[34] = bb; }
    }
    __syncthreads();

    if (tid < NPOS)
        out[(size_t)b * NPOS + tid] = e * (1.f / red[33]);
    if (tid == 0)
        out[(size_t)nb * NPOS + b] = tanhf(red[34] * (0.2f / 32.f)); // tanh(VS*VG*D)
}

extern "C" void kernel_launch(void* const* d_in, const int* in_sizes, int n_in,
                              void* d_out, int out_size)
{
    const float* state = (const float*)d_in[0];
    const int nb = in_sizes[0] / (19 * 19 * 3);
    topo_kernel<<<nb, TPB>>>(state, (float*)d_out, nb);
}

// round 5
// speedup vs baseline: 1.5563x; 1.1468x over previous
#include <cuda_runtime.h>
#include <math.h>

#define TPB    320
#define NPOS   289        // 17*17 core positions
#define TW     28         // padded tile width (27 rows x 28 cols)
#define TCELLS (27*28)

typedef unsigned long long u64;

#define ADD2(d,a,b)   asm("add.rn.f32x2 %0,%1,%2;"    : "=l"(d) : "l"(a), "l"(b))
#define MUL2(d,a,b)   asm("mul.rn.f32x2 %0,%1,%2;"    : "=l"(d) : "l"(a), "l"(b))
#define FMA2(d,a,b,c) asm("fma.rn.f32x2 %0,%1,%2,%3;" : "=l"(d) : "l"(a), "l"(b), "l"(c))
#define UNPK2(x,y,a)  asm("mov.b64 {%0,%1},%2;"       : "=f"(x), "=f"(y) : "l"(a))

__global__ __launch_bounds__(TPB)
void topo_kernel(const float* __restrict__ state, float* __restrict__ out, int nb)
{
    const int b   = blockIdx.x;
    const int tid = threadIdx.x;

    __shared__ float2 g[TCELLS];     // (g0,g1) channel-combined, zero halo
    __shared__ float2 nc6[TCELLS];   // (-6*x0, -6*x1), only core cells read
    __shared__ float  red[64];

    // phase 0a: zero-halo the combined tile
    for (int i = tid; i < TCELLS; i += TPB) g[i] = make_float2(0.f, 0.f);
    __syncthreads();

    // phase 0b: load 19x19x3 NHWC, fold channels
    const float* sp = state + (size_t)b * 1083;
    for (int i = tid; i < 361; i += TPB) {
        int y = i / 19, x = i - y * 19;
        float x0 = sp[3 * i], x1 = sp[3 * i + 1], x2 = sp[3 * i + 2];
        int idx = (y + 4) * TW + (x + 4);
        g[idx]   = make_float2(fmaf(-5.f, x1 + x2, x0), fmaf(-5.f, x0 + x2, x1));
        nc6[idx] = make_float2(-6.f * x0, -6.f * x1);
    }
    __syncthreads();

    float logit, dval;
    if (tid < NPOS) {
        const int py = tid / 17;
        const int px = tid - py * 17;
        const int base = (py + 5) * TW + (px + 5);

        const u64 NC   = *(const u64*)&nc6[base];                 // packed (-6x0,-6x1)
        const u64 Dc   = *(const u64*)&g[base];                   // center cell, shared by all o
        const u64 NEG1 = 0xBF800000BF800000ULL;                   // (-1,-1)
        const u64 AMSK = 0x7FFFFFFF7FFFFFFFULL;

        const int steps[4] = {1, TW, TW + 1, TW - 1};             // H, V, diag, anti-diag
        float sd0 = 0.f, sd1 = 0.f;

        #pragma unroll
        for (int o = 0; o < 4; ++o) {
            const int st = steps[o];
            u64 D0 = *(const u64*)&g[base - 4 * st];
            u64 D1 = *(const u64*)&g[base - 3 * st];
            u64 D2 = *(const u64*)&g[base - 2 * st];
            u64 D3 = *(const u64*)&g[base - 1 * st];
            u64 D5 = *(const u64*)&g[base + 1 * st];
            u64 D6 = *(const u64*)&g[base + 2 * st];
            u64 D7 = *(const u64*)&g[base + 3 * st];
            u64 D8 = *(const u64*)&g[base + 4 * st];

            u64 U;                                 // packed sliding window sum
            ADD2(U, Dc, D5); ADD2(U, U, D6); ADD2(U, U, D7); ADD2(U, U, D8);

            u64 S = 0ULL;                          // packed (+0,+0) accum of (2*relu)^6
            #pragma unroll
            for (int q = 0; q < 5; ++q) {
                if (q == 1) { ADD2(U, U, D3); FMA2(U, D8, NEG1, U); }
                if (q == 2) { ADD2(U, U, D2); FMA2(U, D7, NEG1, U); }
                if (q == 3) { ADD2(U, U, D1); FMA2(U, D6, NEG1, U); }
                if (q == 4) { ADD2(U, U, D0); FMA2(U, D5, NEG1, U); }
                u64 R; ADD2(R, U, NC);             // r = W - 6*center  (packed both streams)
                u64 A = R & AMSK;                  // |r|
                u64 T; ADD2(T, R, A);              // 2*relu(r)  (exact)
                u64 T2; MUL2(T2, T, T);
                u64 T4; MUL2(T4, T2, T2);
                FMA2(S, T4, T2, S);                // += (2 relu)^6 = 64*relu^6
            }
            float s0, s1; UNPK2(s0, s1, S);
            sd0 += (s0 > 0.f) ? __powf(s0, 0.8333333333f) : 0.f;  // ^(5/6); 64^(5/6)=32 folded later
            sd1 += (s1 > 0.f) ? __powf(s1, 0.8333333333f) : 0.f;
        }
        float f0 = (sd0 > 0.f) ? __powf(sd0 * 0.03125f, 0.2f) : 0.f;  // /32 undoes the 2^6 scale
        float f1 = (sd1 > 0.f) ? __powf(sd1 * 0.03125f, 0.2f) : 0.f;
        logit = f0 + f1;
        dval  = f0 - f1;
    } else {
        logit = -INFINITY;
        dval  = 0.f;
    }

    const unsigned FULL = 0xffffffffu;
    const int wid  = tid >> 5;
    const int lane = tid & 31;

    // block max of logits
    float m = logit;
    #pragma unroll
    for (int off = 16; off; off >>= 1)
        m = fmaxf(m, __shfl_xor_sync(FULL, m, off));
    if (lane == 0) red[wid] = m;
    __syncthreads();
    if (tid < 32) {
        float t = (tid < TPB / 32) ? red[tid] : -INFINITY;
        #pragma unroll
        for (int off = 8; off; off >>= 1)
            t = fmaxf(t, __shfl_xor_sync(FULL, t, off));
        if (tid == 0) red[32] = t;
    }
    __syncthreads();
    const float maxv = red[32];

    // sum of exp (softmax denom) and sum of (f0 - f1) (value head)
    float e  = (tid < NPOS) ? __expf(2.f * (logit - maxv)) : 0.f;  // POLICY_STRETCH = 2
    float se = e, sv = dval;
    #pragma unroll
    for (int off = 16; off; off >>= 1) {
        se += __shfl_xor_sync(FULL, se, off);
        sv += __shfl_xor_sync(FULL, sv, off);
    }
    if (lane == 0) { red[wid] = se; red[wid + 16] = sv; }
    __syncthreads();
    if (tid < 32) {
        float a  = (tid < TPB / 32) ? red[tid] : 0.f;
        float bb = (tid < TPB / 32) ? red[tid + 16] : 0.f;
        #pragma unroll
        for (int off = 8; off; off >>= 1) {
            a  += __shfl_xor_sync(FULL, a, off);
            bb += __shfl_xor_sync(FULL, bb, off);
        }
        if (tid == 0) { red[33] = a; red[34] = bb; }
    }
    __syncthreads();

    if (tid < NPOS)
        out[(size_t)b * NPOS + tid] = e * (1.f / red[33]);
    if (tid == 0)
        out[(size_t)nb * NPOS + b] = tanhf(red[34] * (0.2f / 32.f)); // tanh(VS*VG*D)
}

extern "C" void kernel_launch(void* const* d_in, const int* in_sizes, int n_in,
                              void* d_out, int out_size)
{
    const float* state = (const float*)d_in[0];
    const int nb = in_sizes[0] / (19 * 19 * 3);
    topo_kernel<<<nb, TPB>>>(state, (float*)d_out, nb);
}